// round 13
// baseline (speedup 1.0000x reference)
#include <cuda_runtime.h>
#include <stdint.h>

typedef unsigned long long u64;
typedef unsigned int u32;

#define NLEV 5
#define CLSN 16
#define TOPK 1000
#define NTOT 785664
#define KTOT (NLEV * TOPK)
#define HBITS 13
#define HB (1 << HBITS)        /* 8192 bins: ord >> 19 */
#define WCAP 4096
#define CHUNK 1536
#define NCHUNK 512             /* 512*1536 = 786432 >= NTOT */
#define EPB 16                 /* rank: elements per block (2 per warp) */
#define MAXD 4.135166556742356f

__device__ __constant__ int d_off[6] = {0, 589824, 737280, 774144, 783360, 785664};
__device__ __constant__ int d_len[5] = {589824, 147456, 36864, 9216, 2304};

struct Ptrs {
    const float* anc[NLEV];
    const float* cls[NLEV];
    const float* reg[NLEV];
};

// ------- scratch (device globals, zero-initialized at load; k_emit re-zeroes
// g_hist/g_done at the end of every call so the entry invariant holds) -------
__device__ int g_hist[NLEV * HB];
__device__ unsigned g_done;
__device__ int g_nwin[NLEV];        // zeroed by ruler's last block
__device__ u32 g_ord[NTOT];
__device__ u64 g_win[NLEV][WCAP];
__device__ int g_thr[NLEV];
__device__ u32 g_sel[KTOT];

__device__ __forceinline__ int level_of(int a) {
    int l = 0;
#pragma unroll
    for (int j = 1; j < NLEV; j++) l += (a >= d_off[j]);
    return l;
}

// ---- K1: ruler (max of 16 logits) + shared 13-bit histogram; the LAST
//      block (done-counter) also resolves all 5 thresholds (no extra node) ----
__global__ void __launch_bounds__(512)
k_ruler(Ptrs p) {
    __shared__ u32 h[HB];                     // 32 KB (reused as csum by resolver)
    __shared__ unsigned s_rank;
    __shared__ int s_cidx, s_sufnext;
    const int t = threadIdx.x;
    for (int b = t; b < HB; b += 512) h[b] = 0;
    __syncthreads();

    const int cstart = blockIdx.x * CHUNK;
    const int l = level_of(cstart);
    const int base = d_off[l];
    const int iend = (cstart + CHUNK < NTOT) ? cstart + CHUNK : NTOT;
    const float4* cls4 = (const float4*)p.cls[l];

#pragma unroll
    for (int q = 0; q < 3; q++) {
        int a = cstart + q * 512 + t;
        if (a < iend) {
            int i = a - base;
            float4 va = cls4[i * 4 + 0], vb = cls4[i * 4 + 1];
            float4 vc = cls4[i * 4 + 2], vd = cls4[i * 4 + 3];
            float m = fmaxf(fmaxf(fmaxf(va.x, va.y), fmaxf(va.z, va.w)),
                            fmaxf(fmaxf(vb.x, vb.y), fmaxf(vb.z, vb.w)));
            m = fmaxf(m, fmaxf(fmaxf(vc.x, vc.y), fmaxf(vc.z, vc.w)));
            m = fmaxf(m, fmaxf(fmaxf(vd.x, vd.y), fmaxf(vd.z, vd.w)));
            u32 u = __float_as_uint(m);
            u32 ord = (u & 0x80000000u) ? ~u : (u | 0x80000000u);  // monotonic
            g_ord[a] = ord;
            atomicAdd(&h[ord >> (32 - HBITS)], 1u);
        }
    }
    __syncthreads();

    int* gh = &g_hist[l * HB];
    for (int b = t; b < HB; b += 512) {
        u32 c = h[b];
        if (c) atomicAdd(&gh[b], (int)c);     // L2 atomics: globally visible
    }
    __syncthreads();

    if (t == 0) {
        __threadfence();
        s_rank = atomicAdd(&g_done, 1u);
    }
    __syncthreads();
    if (s_rank != NCHUNK - 1) return;

    // ---- last block: zero g_nwin + resolve threshold bin per level ----
    if (t < NLEV) g_nwin[t] = 0;
    int* csum = (int*)h;                      // reuse shared histogram storage
    for (int lv = 0; lv < NLEV; lv++) {
        const int* gh2 = &g_hist[lv * HB];
        const int cb = t * 16;                // 16 bins per thread (512 thr)
        int s = 0;
#pragma unroll
        for (int j = 0; j < 16; j++) s += __ldcg(&gh2[cb + j]);
        __syncthreads();
        csum[t] = s;
        __syncthreads();
        for (int off = 1; off < 512; off <<= 1) {   // reversed scan -> suffix
            int v = csum[t];
            int add = (t + off < 512) ? csum[t + off] : 0;
            __syncthreads();
            csum[t] = v + add;
            __syncthreads();
        }
        if (csum[t] >= TOPK && (t == 511 || csum[t + 1] < TOPK)) {
            s_cidx = t;
            s_sufnext = (t == 511) ? 0 : csum[t + 1];
        }
        __syncthreads();
        if (t == 0) {
            int cbase = s_cidx * 16;
            int suf = s_sufnext, b = cbase + 15;
            for (int j = 15; j >= 0; j--) {
                suf += __ldcg(&gh2[cbase + j]);
                b = cbase + j;
                if (suf >= TOPK) break;
            }
            g_thr[lv] = b;
        }
        __syncthreads();
    }
}

// ---- K2: collect keys with top13 >= threshold (ballot-aggregated) ----
__global__ void __launch_bounds__(512)
k_select() {
    const int t = threadIdx.x;
    const int cstart = blockIdx.x * CHUNK;
    const int l = level_of(cstart);
    const int base = d_off[l];
    const int iend = (cstart + CHUNK < NTOT) ? cstart + CHUNK : NTOT;
    const u32 thr = (u32)g_thr[l];
    const int lane = t & 31;

#pragma unroll
    for (int q = 0; q < 3; q++) {
        int a = cstart + q * 512 + t;
        bool win = false;
        u32 ord = 0;
        if (a < iend) {
            ord = g_ord[a];
            win = (ord >> (32 - HBITS)) >= thr;
        }
        unsigned act = __activemask();
        unsigned mask = __ballot_sync(act, win);
        if (win) {
            int leader = __ffs(mask) - 1;
            int rk = __popc(mask & ((1u << lane) - 1));
            int wbase = 0;
            if (lane == leader) wbase = atomicAdd(&g_nwin[l], __popc(mask));
            wbase = __shfl_sync(mask, wbase, leader);
            int w = wbase + rk;
            if (w < WCAP) g_win[l][w] = ((u64)ord << 32) | (u32)(a - base);
        }
    }
}

// ---- K3: exact rank-select, 2 elements per warp -> g_sel ----
// Keys (~ord, idx) unique -> rank == exact jax top_k position.
__global__ void __launch_bounds__(256)
k_rank() {
    __shared__ u64 s[WCAP];       // typical n ~1250 (10 KB used)
    const int l = blockIdx.y;
    const int t = threadIdx.x;
    const int warp = t >> 5;
    const int lane = t & 31;
    int n = g_nwin[l];
    if (n > WCAP) n = WCAP;
    if (blockIdx.x * EPB >= n) return;        // whole block out of range

    const u64* win = g_win[l];
    for (int i = t; i < n; i += 256)
        s[i] = win[i] ^ 0xFFFFFFFF00000000ULL;   // ascending (~ord, idx)
    __syncthreads();

    const int e0 = blockIdx.x * EPB + warp * 2;
    if (e0 >= n) return;
    const u64 me0 = s[e0];
    const u64 me1 = (e0 + 1 < n) ? s[e0 + 1] : ~0ULL;
    int c0 = 0, c1 = 0;
    for (int j = lane; j < n; j += 32) {      // conflict-free strided LDS
        u64 v = s[j];
        c0 += (v < me0);
        c1 += (v < me1);
    }
    int r0 = __reduce_add_sync(0xFFFFFFFFu, c0);
    int r1 = __reduce_add_sync(0xFFFFFFFFu, c1);
    if (lane == 0) {
        if (r0 < TOPK) {
            u32 idx = (u32)(me0 & 0xFFFFFFFFu);
            if (idx >= (u32)d_len[l]) idx = 0;
            g_sel[l * TOPK + r0] = idx;
        }
        if (e0 + 1 < n && r1 < TOPK) {
            u32 idx = (u32)(me1 & 0xFFFFFFFFu);
            if (idx >= (u32)d_len[l]) idx = 0;
            g_sel[l * TOPK + r1] = idx;
        }
    }
}

// ---- K4: decode + emit (grid 125 x 5, 128 thr); also re-zeroes g_hist
//      and g_done so the next kernel_launch call sees them clean ----
__global__ void __launch_bounds__(128)
k_emit(Ptrs p, float* __restrict__ out) {
    __shared__ float4 bbox[8];
    __shared__ u32 sidx[8];
    const int l = blockIdx.y;
    const int kloc = blockIdx.x * 8;
    const int t = threadIdx.x;

    // cleanup for next call (spread over the 80000 threads of this grid)
    {
        int g = (blockIdx.y * gridDim.x + blockIdx.x) * 128 + t;
        if (g < NLEV * HB) (&g_hist[0])[g] = 0;
        if (g == 0) g_done = 0;
    }

    if (t < 8) {
        u32 idx = g_sel[l * TOPK + kloc + t];
        if (idx >= (u32)d_len[l]) idx = 0;     // safety
        sidx[t] = idx;
        float4 a4 = ((const float4*)p.anc[l])[idx];
        float4 r4 = ((const float4*)p.reg[l])[idx * 2];
        float w = a4.z - a4.x, h = a4.w - a4.y;
        float cx = a4.x + 0.5f * w, cy = a4.y + 0.5f * h;
        float pcx = cx + r4.x * w, pcy = cy + r4.y * h;
        float pw = w * expf(fminf(r4.z, MAXD));
        float ph = h * expf(fminf(r4.w, MAXD));
        bbox[t] = make_float4(pcx - 0.5f * pw, pcy - 0.5f * ph,
                              pcx + 0.5f * pw, pcy + 0.5f * ph);
    }
    __syncthreads();

    const int k = t >> 4;          // 0..7
    const int c = t & 15;
    u32 idx = sidx[k];
    float score = p.cls[l][(size_t)idx * 16 + c];
    float sg = 1.0f / (1.0f + expf(-score));
    float4 b4 = bbox[k];
    float* o = out + ((size_t)(l * TOPK + kloc + k) * CLSN + c) * 6;
    float2* o2 = (float2*)o;
    o2[0] = make_float2(b4.x, b4.y);
    o2[1] = make_float2(b4.z, b4.w);
    o2[2] = make_float2(sg, (float)(c + 1));
}

extern "C" void kernel_launch(void* const* d_in, const int* in_sizes, int n_in,
                              void* d_out, int out_size) {
    (void)in_sizes; (void)n_in; (void)out_size;
    Ptrs p;
    for (int l = 0; l < NLEV; l++) {
        p.anc[l] = (const float*)d_in[3 * l + 0];
        p.cls[l] = (const float*)d_in[3 * l + 1];
        p.reg[l] = (const float*)d_in[3 * l + 2];
    }

    k_ruler<<<NCHUNK, 512>>>(p);
    k_select<<<NCHUNK, 512>>>();
    dim3 gr(WCAP / EPB, NLEV);
    k_rank<<<gr, 256>>>();
    dim3 ge(TOPK / 8, NLEV);
    k_emit<<<ge, 128>>>(p, (float*)d_out);
}

// round 14
// speedup vs baseline: 1.3780x; 1.3780x over previous
#include <cuda_runtime.h>
#include <stdint.h>

typedef unsigned long long u64;
typedef unsigned int u32;

#define NLEV 5
#define CLSN 16
#define TOPK 1000
#define NTOT 785664
#define KTOT (NLEV * TOPK)
#define HBITS 13
#define HB (1 << HBITS)        /* 8192 bins: ord >> 19 */
#define WCAP 4096
#define CHUNK 1536
#define NCHUNK 512             /* 512*1536 = 786432 >= NTOT */
#define MAXD 4.135166556742356f

__device__ __constant__ int d_off[6] = {0, 589824, 737280, 774144, 783360, 785664};
__device__ __constant__ int d_len[5] = {589824, 147456, 36864, 9216, 2304};

struct Ptrs {
    const float* anc[NLEV];
    const float* cls[NLEV];
    const float* reg[NLEV];
};

// ------- scratch (device globals; zero-initialized at load). g_hist is
// re-zeroed by k_rank (which runs after k_resolve consumed it), g_nwin is
// zeroed by k_resolve (before k_select produces into it) — so every
// kernel_launch call, including graph replays, sees the right state. -------
__device__ int g_hist[NLEV * HB];
__device__ int g_nwin[NLEV];
__device__ u32 g_ord[NTOT];
__device__ u64 g_win[NLEV][WCAP];
__device__ int g_thr[NLEV];
__device__ u32 g_sel[KTOT];

__device__ __forceinline__ int level_of(int a) {
    int l = 0;
#pragma unroll
    for (int j = 1; j < NLEV; j++) l += (a >= d_off[j]);
    return l;
}

// ---- K1: ruler (max of 16 logits) + PRIVATE shared 13-bit histogram ----
__global__ void __launch_bounds__(512)
k_ruler(Ptrs p) {
    __shared__ u32 h[HB];                     // 32 KB
    const int t = threadIdx.x;
    for (int b = t; b < HB; b += 512) h[b] = 0;
    __syncthreads();

    const int cstart = blockIdx.x * CHUNK;
    const int l = level_of(cstart);
    const int base = d_off[l];
    const int iend = (cstart + CHUNK < NTOT) ? cstart + CHUNK : NTOT;
    const float4* cls4 = (const float4*)p.cls[l];

#pragma unroll
    for (int q = 0; q < 3; q++) {
        int a = cstart + q * 512 + t;
        if (a < iend) {
            int i = a - base;
            float4 va = cls4[i * 4 + 0], vb = cls4[i * 4 + 1];
            float4 vc = cls4[i * 4 + 2], vd = cls4[i * 4 + 3];
            float m = fmaxf(fmaxf(fmaxf(va.x, va.y), fmaxf(va.z, va.w)),
                            fmaxf(fmaxf(vb.x, vb.y), fmaxf(vb.z, vb.w)));
            m = fmaxf(m, fmaxf(fmaxf(vc.x, vc.y), fmaxf(vc.z, vc.w)));
            m = fmaxf(m, fmaxf(fmaxf(vd.x, vd.y), fmaxf(vd.z, vd.w)));
            u32 u = __float_as_uint(m);
            u32 ord = (u & 0x80000000u) ? ~u : (u | 0x80000000u);  // monotonic
            g_ord[a] = ord;
            atomicAdd(&h[ord >> (32 - HBITS)], 1u);
        }
    }
    __syncthreads();

    int* gh = &g_hist[l * HB];
    for (int b = t; b < HB; b += 512) {
        u32 c = h[b];
        if (c) atomicAdd(&gh[b], (int)c);     // <=384 adds per address
    }
}

// ---- K2: per-level threshold bin + zero g_nwin ----
__global__ void k_resolve() {
    const int l = blockIdx.x;
    const int t = threadIdx.x;                // 256 threads
    const int CH = HB / 256;                  // 32 bins/thread
    __shared__ int csum[256];
    __shared__ int s_cidx, s_sufnext;
    const int* h = &g_hist[l * HB];

    if (t == 0) g_nwin[l] = 0;                // consumed only by k_select (later)

    int base = t * CH, s = 0;
#pragma unroll 4
    for (int j = 0; j < CH; j++) s += h[base + j];
    csum[t] = s;
    __syncthreads();
    for (int off = 1; off < 256; off <<= 1) { // reversed scan -> suffix sums
        int v = csum[t];
        int add = (t + off < 256) ? csum[t + off] : 0;
        __syncthreads();
        csum[t] = v + add;
        __syncthreads();
    }
    if (csum[t] >= TOPK && (t == 255 || csum[t + 1] < TOPK)) {
        s_cidx = t;
        s_sufnext = (t == 255) ? 0 : csum[t + 1];
    }
    __syncthreads();
    if (t == 0) {
        int cbase = s_cidx * CH;
        int suf = s_sufnext, b = cbase + CH - 1;
        for (int j = CH - 1; j >= 0; j--) {
            suf += h[cbase + j];
            b = cbase + j;
            if (suf >= TOPK) break;
        }
        g_thr[l] = b;
    }
}

// ---- K3: collect keys with top13 >= threshold (ballot-aggregated) ----
__global__ void __launch_bounds__(512)
k_select() {
    const int t = threadIdx.x;
    const int cstart = blockIdx.x * CHUNK;
    const int l = level_of(cstart);
    const int base = d_off[l];
    const int iend = (cstart + CHUNK < NTOT) ? cstart + CHUNK : NTOT;
    const u32 thr = (u32)g_thr[l];
    const int lane = t & 31;

#pragma unroll
    for (int q = 0; q < 3; q++) {
        int a = cstart + q * 512 + t;
        bool win = false;
        u32 ord = 0;
        if (a < iend) {
            ord = g_ord[a];
            win = (ord >> (32 - HBITS)) >= thr;
        }
        unsigned act = __activemask();
        unsigned mask = __ballot_sync(act, win);
        if (win) {
            int leader = __ffs(mask) - 1;
            int rk = __popc(mask & ((1u << lane) - 1));
            int wbase = 0;
            if (lane == leader) wbase = atomicAdd(&g_nwin[l], __popc(mask));
            wbase = __shfl_sync(mask, wbase, leader);
            int w = wbase + rk;
            if (w < WCAP) g_win[l][w] = ((u64)ord << 32) | (u32)(a - base);
        }
    }
}

// ---- K4: warp-per-element exact rank-select -> g_sel; ALSO zeroes g_hist
//      for the next call (it runs after k_resolve consumed the histogram).
// grid (WCAP/8, NLEV), block 256 = 8 warps. Warp w ranks element
// e = blockIdx.x*8 + w. Keys (~ord, idx) unique -> exact jax top_k position.
__global__ void __launch_bounds__(256)
k_rank() {
    __shared__ u64 s[WCAP];       // 32 KB worst case; typical n ~1250
    const int l = blockIdx.y;
    const int t = threadIdx.x;
    const int warp = t >> 5;
    const int lane = t & 31;

    // cleanup for next call (spread over all 2560 blocks; mostly idle ones)
    {
        int g = (blockIdx.y * gridDim.x + blockIdx.x) * 256 + t;
        if (g < NLEV * HB) g_hist[g] = 0;
    }

    int n = g_nwin[l];
    if (n > WCAP) n = WCAP;
    if (blockIdx.x * 8 >= n) return;          // whole block out of range

    const u64* win = g_win[l];
    for (int i = t; i < n; i += 256)
        s[i] = win[i] ^ 0xFFFFFFFF00000000ULL;   // ascending (~ord, idx)
    __syncthreads();

    const int e = blockIdx.x * 8 + warp;
    if (e >= n) return;
    const u64 me = s[e];
    int cnt = 0;
    for (int j = lane; j < n; j += 32)        // conflict-free strided LDS
        cnt += (s[j] < me);
    int rank = __reduce_add_sync(0xFFFFFFFFu, cnt);

    if (lane == 0 && rank < TOPK) {
        u32 idx = (u32)(me & 0xFFFFFFFFu);
        if (idx >= (u32)d_len[l]) idx = 0;    // safety (never hit on valid data)
        g_sel[l * TOPK + rank] = idx;
    }
}

// ---- K5: decode + emit, massively parallel (grid 125 x 5, 128 thr) ----
__global__ void __launch_bounds__(128)
k_emit(Ptrs p, float* __restrict__ out) {
    __shared__ float4 bbox[8];
    __shared__ u32 sidx[8];
    const int l = blockIdx.y;
    const int kloc = blockIdx.x * 8;
    const int t = threadIdx.x;

    if (t < 8) {
        u32 idx = g_sel[l * TOPK + kloc + t];
        if (idx >= (u32)d_len[l]) idx = 0;     // safety
        sidx[t] = idx;
        float4 a4 = ((const float4*)p.anc[l])[idx];
        float4 r4 = ((const float4*)p.reg[l])[idx * 2];
        float w = a4.z - a4.x, h = a4.w - a4.y;
        float cx = a4.x + 0.5f * w, cy = a4.y + 0.5f * h;
        float pcx = cx + r4.x * w, pcy = cy + r4.y * h;
        float pw = w * expf(fminf(r4.z, MAXD));
        float ph = h * expf(fminf(r4.w, MAXD));
        bbox[t] = make_float4(pcx - 0.5f * pw, pcy - 0.5f * ph,
                              pcx + 0.5f * pw, pcy + 0.5f * ph);
    }
    __syncthreads();

    const int k = t >> 4;          // 0..7
    const int c = t & 15;
    u32 idx = sidx[k];
    float score = p.cls[l][(size_t)idx * 16 + c];
    float sg = 1.0f / (1.0f + expf(-score));
    float4 b4 = bbox[k];
    float* o = out + ((size_t)(l * TOPK + kloc + k) * CLSN + c) * 6;
    float2* o2 = (float2*)o;
    o2[0] = make_float2(b4.x, b4.y);
    o2[1] = make_float2(b4.z, b4.w);
    o2[2] = make_float2(sg, (float)(c + 1));
}

extern "C" void kernel_launch(void* const* d_in, const int* in_sizes, int n_in,
                              void* d_out, int out_size) {
    (void)in_sizes; (void)n_in; (void)out_size;
    Ptrs p;
    for (int l = 0; l < NLEV; l++) {
        p.anc[l] = (const float*)d_in[3 * l + 0];
        p.cls[l] = (const float*)d_in[3 * l + 1];
        p.reg[l] = (const float*)d_in[3 * l + 2];
    }

    k_ruler<<<NCHUNK, 512>>>(p);
    k_resolve<<<NLEV, 256>>>();
    k_select<<<NCHUNK, 512>>>();
    dim3 gr(WCAP / 8, NLEV);
    k_rank<<<gr, 256>>>();
    dim3 ge(TOPK / 8, NLEV);
    k_emit<<<ge, 128>>>(p, (float*)d_out);
}